// round 14
// baseline (speedup 1.0000x reference)
#include <cuda_runtime.h>
#include <cuda_fp16.h>

#define NPIX   (480*480)
#define NCLS   124
#define FCH    64
#define IN_HW  120
#define EPS_F  1e-8f
#define GRID   444        // 148 SMs x 3 co-resident
#define NBIN   80         // bin blocks [364,444): hist+scan+scatter among themselves
#define BINPX  2880       // 80*2880 = 230400
#define CH_    519        // k_main per-block range

// ---------------- device scratch (zero at first entry; restored each run) ----
__device__ __align__(16) __half g_feats_h[IN_HW*IN_HW*FCH];  // [y][x][c] fp16
__device__ __align__(16) float g_mn[NCLS*FCH];
__device__ float g_iszero[NCLS];
__device__ int   g_hist[NCLS];          // reset by k_main finalizer
__device__ int   g_cursor[NCLS];        // reset by k_main finalizer
__device__ int   g_binned[NPIX];        // pix | (cls<<18), class-contiguous
__device__ __align__(16) float g_sum[NCLS*FCH];
__device__ __align__(16) float g_wx[NCLS*FCH];
__device__ float g_wsum[NCLS];

__device__ int      g_bar_count = 0;    // bin-block barrier (reset by scanner)
__device__ unsigned g_bar_gen   = 0;    // monotonic across replays
__device__ int      g_done      = 0;    // k_main completion counter (reset by finalizer)

__constant__ float c_frac[4] = {0.625f, 0.875f, 0.125f, 0.375f};

__device__ __forceinline__ __half2 u2h2(const unsigned& u) {
    return *reinterpret_cast<const __half2*>(&u);
}

// ---------------- K1: transpose | setup | bin(hist->bar+scan->scatter) -------
__global__ void __launch_bounds__(256, 3)
k_pre(const float* __restrict__ feats, const float* __restrict__ memory,
      const int* __restrict__ seg) {
    __shared__ float tile[FCH*61];   // transpose buffer / bin scan scratch
    __shared__ int   h[128];
    __shared__ int      s_who;
    __shared__ unsigned s_gen;
    const int b = blockIdx.x;
    const int t = threadIdx.x;

    if (b < 240) {                   // ---- transpose half-row -> fp16, exit ----
        const int y  = b >> 1;
        const int xh = (b & 1) * 60;
        for (int i = t; i < FCH*60; i += 256) {
            int c = i / 60, x = i - c*60;
            tile[c*61 + x] = feats[c*IN_HW*IN_HW + y*IN_HW + xh + x];
        }
        __syncthreads();
        for (int i = t; i < 60*FCH; i += 256) {
            int x = i >> 6, c = i & 63;
            g_feats_h[(y*IN_HW + xh + x)*FCH + c] = __float2half(tile[c*61 + x]);
        }
        return;
    }
    if (b < 364) {                   // ---- setup class b-240, exit ----
        const int c = b - 240;
        if (t < 32) {
            float v0 = memory[c*FCH + t];
            float v1 = memory[c*FCH + t + 32];
            float s = v0*v0 + v1*v1;
            #pragma unroll
            for (int o = 16; o; o >>= 1) s += __shfl_xor_sync(0xffffffffu, s, o);
            float inv = 1.0f / fmaxf(sqrtf(s), EPS_F);
            g_mn[c*FCH + t]      = v0 * inv;
            g_mn[c*FCH + t + 32] = v1 * inv;
            if (t == 0) {
                g_iszero[c] = (s == 0.0f) ? 1.0f : 0.0f;
                g_wsum[c] = 0.0f;
            }
        } else if (t < 96) {
            g_sum[c*FCH + (t - 32)] = 0.0f;
            g_wx [c*FCH + (t - 32)] = 0.0f;
        }
        return;
    }

    // ---- bin blocks [364,444): hist -> barrier(80)+scan -> reserve -> scatter
    const int base = (b - 364) * BINPX;
    if (t < 128) h[t] = 0;
    __syncthreads();
    for (int i = t; i < BINPX; i += 256)
        atomicAdd(&h[seg[base + i]], 1);
    __syncthreads();
    if (t < NCLS && h[t]) atomicAdd(&g_hist[t], h[t]);   // RED (no return)

    // barrier among the 80 bin blocks only; last arriver's block scans
    __threadfence();
    if (t == 0) {
        unsigned my = *(volatile unsigned*)&g_bar_gen;
        s_gen = my;
        int old = atomicAdd(&g_bar_count, 1);
        s_who = (old == NBIN - 1);
        if (!s_who) {
            while (*(volatile unsigned*)&g_bar_gen == my) __nanosleep(32);
        }
        __threadfence();
    }
    __syncthreads();
    if (s_who) {
        int* sc = (int*)tile;
        int hv = 0;
        if (t < 128) { hv = (t < NCLS) ? g_hist[t] : 0; sc[t] = hv; }
        __syncthreads();
        #pragma unroll
        for (int o = 1; o < 128; o <<= 1) {
            int u = (t < 128 && t >= o) ? sc[t - o] : 0;
            __syncthreads();
            if (t < 128) sc[t] += u;
            __syncthreads();
        }
        if (t < NCLS) g_cursor[t] = sc[t] - hv;          // exclusive prefix
        __threadfence();
        __syncthreads();
        if (t == 0) {
            g_bar_count = 0;
            __threadfence();
            *(volatile unsigned*)&g_bar_gen = s_gen + 1;
        }
    }
    __syncthreads();

    if (t < NCLS) {                                       // depth-80 reservation
        int cnt = h[t];
        h[t] = cnt ? atomicAdd(&g_cursor[t], cnt) : 0;
    }
    __syncthreads();
    for (int i = t; i < BINPX; i += 256) {
        int pix = base + i;
        int c = seg[pix];
        int slot = atomicAdd(&h[c], 1);                   // smem cursor
        g_binned[slot] = pix | (c << 18);
    }
}

// ---------------- K2: main (frozen R10 body) + last-block finalize ----------
__global__ void __launch_bounds__(256, 3)
k_main(const float* __restrict__ memory, float* __restrict__ out) {
    __shared__ float tile[FCH*61];
    __shared__ int   s_last;
    const int b = blockIdx.x;
    const int t = threadIdx.x;

    int* sbuf = (int*)tile;
    const int start = b * CH_;
    const int n     = min(CH_, NPIX - start);
    for (int i = t; i < n; i += 256) sbuf[i] = g_binned[start + i];
    __syncthreads();

    const int lane = t & 31;
    const int sub  = lane >> 3;
    const int sl   = lane & 7;
    const int w    = t >> 5;
    const int wch  = (n + 7) >> 3;
    const int lj0  = w * wch;
    const int ljend = min(lj0 + wch, n);

    if (lj0 < ljend) {
        const uint4* __restrict__ fth = (const uint4*)g_feats_h;
        const float4* __restrict__ mn4 = (const float4*)g_mn;

        float4 sA = {0,0,0,0}, sB = {0,0,0,0}, wA = {0,0,0,0}, wB = {0,0,0,0};
        float  aw = 0.f;
        float4 mA = {0,0,0,0}, mB = {0,0,0,0};
        int cur = -1;

        for (int lj = lj0; lj < ljend; lj += 4) {
            const int idx    = lj + sub;
            const bool valid = idx < ljend;
            const int packed = sbuf[valid ? idx : (ljend - 1)];
            const int cls = packed >> 18;
            const int pix = packed & 0x3FFFF;

            const int oy = pix / 480;
            const int ox = pix - oy*480;
            const int iy0 = (oy >> 2) + ((oy >> 1) & 1) - 1;
            const int ix0 = (ox >> 2) + ((ox >> 1) & 1) - 1;
            const float fy = c_frac[oy & 3];
            const float fx = c_frac[ox & 3];
            const int y0 = max(iy0, 0), y1 = min(iy0 + 1, IN_HW - 1);
            const int x0 = max(ix0, 0), x1 = min(ix0 + 1, IN_HW - 1);
            const float w11 = fy * fx;
            const float w10 = fy - w11;
            const float w01 = fx - w11;
            const float w00 = 1.0f - fy - fx + w11;

            const int rA = (y0*IN_HW + x0)*8, rB = (y0*IN_HW + x1)*8;
            const int rC = (y1*IN_HW + x0)*8, rD = (y1*IN_HW + x1)*8;
            const uint4 A = fth[rA + sl], B = fth[rB + sl];
            const uint4 C = fth[rC + sl], D = fth[rD + sl];

            if (__any_sync(0xffffffffu, cls != cur)) {
                if (cls != cur) {
                    if (cur >= 0) {
                        atomicAdd((float4*)&g_sum[cur*FCH + 8*sl],     sA);
                        atomicAdd((float4*)&g_sum[cur*FCH + 8*sl + 4], sB);
                        atomicAdd((float4*)&g_wx [cur*FCH + 8*sl],     wA);
                        atomicAdd((float4*)&g_wx [cur*FCH + 8*sl + 4], wB);
                        if (sl == 0) atomicAdd(&g_wsum[cur], aw);
                    }
                    sA = make_float4(0,0,0,0); sB = make_float4(0,0,0,0);
                    wA = make_float4(0,0,0,0); wB = make_float4(0,0,0,0);
                    aw = 0.f;
                    cur = cls;
                    mA = mn4[cls*16 + 2*sl];
                    mB = mn4[cls*16 + 2*sl + 1];
                }
            }

            const __half2 hw00 = __float2half2_rn(w00);
            const __half2 hw01 = __float2half2_rn(w01);
            const __half2 hw10 = __float2half2_rn(w10);
            const __half2 hw11 = __float2half2_rn(w11);

            __half2 h0 = __hmul2(hw00, u2h2(A.x));
            h0 = __hfma2(hw01, u2h2(B.x), h0);
            h0 = __hfma2(hw10, u2h2(C.x), h0);
            h0 = __hfma2(hw11, u2h2(D.x), h0);
            __half2 h1 = __hmul2(hw00, u2h2(A.y));
            h1 = __hfma2(hw01, u2h2(B.y), h1);
            h1 = __hfma2(hw10, u2h2(C.y), h1);
            h1 = __hfma2(hw11, u2h2(D.y), h1);
            __half2 h2 = __hmul2(hw00, u2h2(A.z));
            h2 = __hfma2(hw01, u2h2(B.z), h2);
            h2 = __hfma2(hw10, u2h2(C.z), h2);
            h2 = __hfma2(hw11, u2h2(D.z), h2);
            __half2 h3 = __hmul2(hw00, u2h2(A.w));
            h3 = __hfma2(hw01, u2h2(B.w), h3);
            h3 = __hfma2(hw10, u2h2(C.w), h3);
            h3 = __hfma2(hw11, u2h2(D.w), h3);

            const float2 f0 = __half22float2(h0);
            const float2 f1 = __half22float2(h1);
            const float2 f2 = __half22float2(h2);
            const float2 f3 = __half22float2(h3);

            float nsq = f0.x*f0.x + f0.y*f0.y + f1.x*f1.x + f1.y*f1.y
                      + f2.x*f2.x + f2.y*f2.y + f3.x*f3.x + f3.y*f3.y;
            float dt  = f0.x*mA.x + f0.y*mA.y + f1.x*mA.z + f1.y*mA.w
                      + f2.x*mB.x + f2.y*mB.y + f3.x*mB.z + f3.y*mB.w;
            #pragma unroll
            for (int o = 4; o; o >>= 1) {
                nsq += __shfl_xor_sync(0xffffffffu, nsq, o);
                dt  += __shfl_xor_sync(0xffffffffu, dt,  o);
            }
            const float wgt = 1.0f - dt * rsqrtf(fmaxf(nsq, 1e-16f));
            const float vv = valid ? 1.0f : 0.0f;
            const float g  = valid ? wgt : 0.0f;

            sA.x = fmaf(vv, f0.x, sA.x); sA.y = fmaf(vv, f0.y, sA.y);
            sA.z = fmaf(vv, f1.x, sA.z); sA.w = fmaf(vv, f1.y, sA.w);
            sB.x = fmaf(vv, f2.x, sB.x); sB.y = fmaf(vv, f2.y, sB.y);
            sB.z = fmaf(vv, f3.x, sB.z); sB.w = fmaf(vv, f3.y, sB.w);
            wA.x = fmaf(g, f0.x, wA.x);  wA.y = fmaf(g, f0.y, wA.y);
            wA.z = fmaf(g, f1.x, wA.z);  wA.w = fmaf(g, f1.y, wA.w);
            wB.x = fmaf(g, f2.x, wB.x);  wB.y = fmaf(g, f2.y, wB.y);
            wB.z = fmaf(g, f3.x, wB.z);  wB.w = fmaf(g, f3.y, wB.w);
            aw += g;
        }

        if (cur >= 0) {
            atomicAdd((float4*)&g_sum[cur*FCH + 8*sl],     sA);
            atomicAdd((float4*)&g_sum[cur*FCH + 8*sl + 4], sB);
            atomicAdd((float4*)&g_wx [cur*FCH + 8*sl],     wA);
            atomicAdd((float4*)&g_wx [cur*FCH + 8*sl + 4], wB);
            if (sl == 0) atomicAdd(&g_wsum[cur], aw);
        }
    }

    // ---- last finished block finalizes (atomics are L2-coherent; __ldcg) ----
    __threadfence();
    __syncthreads();
    if (t == 0) s_last = (atomicAdd(&g_done, 1) == GRID - 1);
    __syncthreads();
    if (s_last) {
        __threadfence();
        for (int i = t; i < NCLS*FCH; i += 256) {
            const int c  = i >> 6;
            const int ch = i & 63;
            const int cnt = __ldcg(&g_hist[c]);
            const float memv = memory[i];
            float res = memv;
            if (cnt > 0) {
                if (g_iszero[c] != 0.0f) {
                    res = __ldcg(&g_sum[i]) / fmaxf((float)cnt, 1.0f);
                } else {
                    const float ws = __ldcg(&g_wsum[c]);
                    const float weighted = __ldcg(&g_wx[i]) / ((ws != 0.0f) ? ws : 1.0f);
                    res = 0.9f * memv + 0.1f * weighted;
                }
            }
            out[i] = res;
            (void)ch;
        }
        __syncthreads();
        for (int i = t; i < NCLS; i += 256) { g_hist[i] = 0; g_cursor[i] = 0; }
        if (t == 0) g_done = 0;
    }
}

// ---------------- launch ----------------
extern "C" void kernel_launch(void* const* d_in, const int* in_sizes, int n_in,
                              void* d_out, int out_size) {
    const float* feats  = (const float*)d_in[0];
    const float* memory = (const float*)d_in[1];
    const int*   seg    = (const int*)  d_in[2];
    float* out = (float*)d_out;
    k_pre <<<GRID, 256>>>(feats, memory, seg);
    k_main<<<GRID, 256>>>(memory, out);
}

// round 16
// speedup vs baseline: 1.4224x; 1.4224x over previous
#include <cuda_runtime.h>
#include <cuda_fp16.h>

#define NPIX   (480*480)
#define NCLS   124
#define FCH    64
#define IN_HW  120
#define EPS_F  1e-8f
#define GRID   444        // 148 SMs x 3 co-resident
#define NBIN   80         // bin blocks [364,444): hist+scan+scatter among themselves
#define BINPX  2880       // 80*2880 = 230400
#define CH_    519        // k_main per-block range

// ---------------- device scratch (zero at first entry; restored each run) ----
__device__ __align__(16) __half g_feats_h[IN_HW*IN_HW*FCH];  // [y][x][c] fp16
__device__ __align__(16) float g_mn[NCLS*FCH];
__device__ float g_iszero[NCLS];
__device__ int   g_hist[NCLS];          // reset in k_fin
__device__ int   g_cursor[NCLS];        // reset in k_fin
__device__ int   g_binned[NPIX];        // pix | (cls<<18), class-contiguous
__device__ __align__(16) float g_sum[NCLS*FCH];
__device__ __align__(16) float g_wx[NCLS*FCH];
__device__ float g_wsum[NCLS];

__device__ int      g_bar_count = 0;    // bin-block barrier (reset by scanner)
__device__ unsigned g_bar_gen   = 0;    // monotonic across replays

__constant__ float c_frac[4] = {0.625f, 0.875f, 0.125f, 0.375f};

__device__ __forceinline__ __half2 u2h2(const unsigned& u) {
    return *reinterpret_cast<const __half2*>(&u);
}

// ---------------- K1: transpose | setup | bin(hist->bar(80)+scan->scatter) ---
// (R14 version verbatim -- measured ~5us)
__global__ void __launch_bounds__(256, 3)
k_pre(const float* __restrict__ feats, const float* __restrict__ memory,
      const int* __restrict__ seg) {
    __shared__ float tile[FCH*61];   // transpose buffer / bin scan scratch
    __shared__ int   h[128];
    __shared__ int      s_who;
    __shared__ unsigned s_gen;
    const int b = blockIdx.x;
    const int t = threadIdx.x;

    if (b < 240) {                   // ---- transpose half-row -> fp16, exit ----
        const int y  = b >> 1;
        const int xh = (b & 1) * 60;
        for (int i = t; i < FCH*60; i += 256) {
            int c = i / 60, x = i - c*60;
            tile[c*61 + x] = feats[c*IN_HW*IN_HW + y*IN_HW + xh + x];
        }
        __syncthreads();
        for (int i = t; i < 60*FCH; i += 256) {
            int x = i >> 6, c = i & 63;
            g_feats_h[(y*IN_HW + xh + x)*FCH + c] = __float2half(tile[c*61 + x]);
        }
        return;
    }
    if (b < 364) {                   // ---- setup class b-240, exit ----
        const int c = b - 240;
        if (t < 32) {
            float v0 = memory[c*FCH + t];
            float v1 = memory[c*FCH + t + 32];
            float s = v0*v0 + v1*v1;
            #pragma unroll
            for (int o = 16; o; o >>= 1) s += __shfl_xor_sync(0xffffffffu, s, o);
            float inv = 1.0f / fmaxf(sqrtf(s), EPS_F);
            g_mn[c*FCH + t]      = v0 * inv;
            g_mn[c*FCH + t + 32] = v1 * inv;
            if (t == 0) {
                g_iszero[c] = (s == 0.0f) ? 1.0f : 0.0f;
                g_wsum[c] = 0.0f;
            }
        } else if (t < 96) {
            g_sum[c*FCH + (t - 32)] = 0.0f;
            g_wx [c*FCH + (t - 32)] = 0.0f;
        }
        return;
    }

    // ---- bin blocks [364,444): hist -> barrier(80)+scan -> reserve -> scatter
    const int base = (b - 364) * BINPX;
    if (t < 128) h[t] = 0;
    __syncthreads();
    for (int i = t; i < BINPX; i += 256)
        atomicAdd(&h[seg[base + i]], 1);
    __syncthreads();
    if (t < NCLS && h[t]) atomicAdd(&g_hist[t], h[t]);   // RED (no return)

    // barrier among the 80 bin blocks only; last arriver's block scans
    __threadfence();
    if (t == 0) {
        unsigned my = *(volatile unsigned*)&g_bar_gen;
        s_gen = my;
        int old = atomicAdd(&g_bar_count, 1);
        s_who = (old == NBIN - 1);
        if (!s_who) {
            while (*(volatile unsigned*)&g_bar_gen == my) __nanosleep(32);
        }
        __threadfence();
    }
    __syncthreads();
    if (s_who) {
        int* sc = (int*)tile;
        int hv = 0;
        if (t < 128) { hv = (t < NCLS) ? g_hist[t] : 0; sc[t] = hv; }
        __syncthreads();
        #pragma unroll
        for (int o = 1; o < 128; o <<= 1) {
            int u = (t < 128 && t >= o) ? sc[t - o] : 0;
            __syncthreads();
            if (t < 128) sc[t] += u;
            __syncthreads();
        }
        if (t < NCLS) g_cursor[t] = sc[t] - hv;          // exclusive prefix
        __threadfence();
        __syncthreads();
        if (t == 0) {
            g_bar_count = 0;
            __threadfence();
            *(volatile unsigned*)&g_bar_gen = s_gen + 1;
        }
    }
    __syncthreads();

    if (t < NCLS) {                                       // depth-80 reservation
        int cnt = h[t];
        h[t] = cnt ? atomicAdd(&g_cursor[t], cnt) : 0;
    }
    __syncthreads();
    for (int i = t; i < BINPX; i += 256) {
        int pix = base + i;
        int c = seg[pix];
        int slot = atomicAdd(&h[c], 1);                   // smem cursor
        g_binned[slot] = pix | (c << 18);
    }
}

// ---------------- K2: main (R13 version VERBATIM -- no params, no tail) ------
__global__ void __launch_bounds__(256, 3) k_main() {
    __shared__ float tile[FCH*61];
    const int b = blockIdx.x;
    const int t = threadIdx.x;

    int* sbuf = (int*)tile;
    const int start = b * CH_;
    const int n     = min(CH_, NPIX - start);
    for (int i = t; i < n; i += 256) sbuf[i] = g_binned[start + i];
    __syncthreads();

    const int lane = t & 31;
    const int sub  = lane >> 3;
    const int sl   = lane & 7;
    const int w    = t >> 5;
    const int wch  = (n + 7) >> 3;
    const int lj0  = w * wch;
    const int ljend = min(lj0 + wch, n);

    if (lj0 < ljend) {
        const uint4* __restrict__ fth = (const uint4*)g_feats_h;
        const float4* __restrict__ mn4 = (const float4*)g_mn;

        float4 sA = {0,0,0,0}, sB = {0,0,0,0}, wA = {0,0,0,0}, wB = {0,0,0,0};
        float  aw = 0.f;
        float4 mA = {0,0,0,0}, mB = {0,0,0,0};
        int cur = -1;

        for (int lj = lj0; lj < ljend; lj += 4) {
            const int idx    = lj + sub;
            const bool valid = idx < ljend;
            const int packed = sbuf[valid ? idx : (ljend - 1)];
            const int cls = packed >> 18;
            const int pix = packed & 0x3FFFF;

            const int oy = pix / 480;
            const int ox = pix - oy*480;
            const int iy0 = (oy >> 2) + ((oy >> 1) & 1) - 1;
            const int ix0 = (ox >> 2) + ((ox >> 1) & 1) - 1;
            const float fy = c_frac[oy & 3];
            const float fx = c_frac[ox & 3];
            const int y0 = max(iy0, 0), y1 = min(iy0 + 1, IN_HW - 1);
            const int x0 = max(ix0, 0), x1 = min(ix0 + 1, IN_HW - 1);
            const float w11 = fy * fx;
            const float w10 = fy - w11;
            const float w01 = fx - w11;
            const float w00 = 1.0f - fy - fx + w11;

            const int rA = (y0*IN_HW + x0)*8, rB = (y0*IN_HW + x1)*8;
            const int rC = (y1*IN_HW + x0)*8, rD = (y1*IN_HW + x1)*8;
            const uint4 A = fth[rA + sl], B = fth[rB + sl];
            const uint4 C = fth[rC + sl], D = fth[rD + sl];

            if (__any_sync(0xffffffffu, cls != cur)) {
                if (cls != cur) {
                    if (cur >= 0) {
                        atomicAdd((float4*)&g_sum[cur*FCH + 8*sl],     sA);
                        atomicAdd((float4*)&g_sum[cur*FCH + 8*sl + 4], sB);
                        atomicAdd((float4*)&g_wx [cur*FCH + 8*sl],     wA);
                        atomicAdd((float4*)&g_wx [cur*FCH + 8*sl + 4], wB);
                        if (sl == 0) atomicAdd(&g_wsum[cur], aw);
                    }
                    sA = make_float4(0,0,0,0); sB = make_float4(0,0,0,0);
                    wA = make_float4(0,0,0,0); wB = make_float4(0,0,0,0);
                    aw = 0.f;
                    cur = cls;
                    mA = mn4[cls*16 + 2*sl];
                    mB = mn4[cls*16 + 2*sl + 1];
                }
            }

            const __half2 hw00 = __float2half2_rn(w00);
            const __half2 hw01 = __float2half2_rn(w01);
            const __half2 hw10 = __float2half2_rn(w10);
            const __half2 hw11 = __float2half2_rn(w11);

            __half2 h0 = __hmul2(hw00, u2h2(A.x));
            h0 = __hfma2(hw01, u2h2(B.x), h0);
            h0 = __hfma2(hw10, u2h2(C.x), h0);
            h0 = __hfma2(hw11, u2h2(D.x), h0);
            __half2 h1 = __hmul2(hw00, u2h2(A.y));
            h1 = __hfma2(hw01, u2h2(B.y), h1);
            h1 = __hfma2(hw10, u2h2(C.y), h1);
            h1 = __hfma2(hw11, u2h2(D.y), h1);
            __half2 h2 = __hmul2(hw00, u2h2(A.z));
            h2 = __hfma2(hw01, u2h2(B.z), h2);
            h2 = __hfma2(hw10, u2h2(C.z), h2);
            h2 = __hfma2(hw11, u2h2(D.z), h2);
            __half2 h3 = __hmul2(hw00, u2h2(A.w));
            h3 = __hfma2(hw01, u2h2(B.w), h3);
            h3 = __hfma2(hw10, u2h2(C.w), h3);
            h3 = __hfma2(hw11, u2h2(D.w), h3);

            const float2 f0 = __half22float2(h0);
            const float2 f1 = __half22float2(h1);
            const float2 f2 = __half22float2(h2);
            const float2 f3 = __half22float2(h3);

            float nsq = f0.x*f0.x + f0.y*f0.y + f1.x*f1.x + f1.y*f1.y
                      + f2.x*f2.x + f2.y*f2.y + f3.x*f3.x + f3.y*f3.y;
            float dt  = f0.x*mA.x + f0.y*mA.y + f1.x*mA.z + f1.y*mA.w
                      + f2.x*mB.x + f2.y*mB.y + f3.x*mB.z + f3.y*mB.w;
            #pragma unroll
            for (int o = 4; o; o >>= 1) {
                nsq += __shfl_xor_sync(0xffffffffu, nsq, o);
                dt  += __shfl_xor_sync(0xffffffffu, dt,  o);
            }
            const float wgt = 1.0f - dt * rsqrtf(fmaxf(nsq, 1e-16f));
            const float vv = valid ? 1.0f : 0.0f;
            const float g  = valid ? wgt : 0.0f;

            sA.x = fmaf(vv, f0.x, sA.x); sA.y = fmaf(vv, f0.y, sA.y);
            sA.z = fmaf(vv, f1.x, sA.z); sA.w = fmaf(vv, f1.y, sA.w);
            sB.x = fmaf(vv, f2.x, sB.x); sB.y = fmaf(vv, f2.y, sB.y);
            sB.z = fmaf(vv, f3.x, sB.z); sB.w = fmaf(vv, f3.y, sB.w);
            wA.x = fmaf(g, f0.x, wA.x);  wA.y = fmaf(g, f0.y, wA.y);
            wA.z = fmaf(g, f1.x, wA.z);  wA.w = fmaf(g, f1.y, wA.w);
            wB.x = fmaf(g, f2.x, wB.x);  wB.y = fmaf(g, f2.y, wB.y);
            wB.z = fmaf(g, f3.x, wB.z);  wB.w = fmaf(g, f3.y, wB.w);
            aw += g;
        }

        if (cur >= 0) {
            atomicAdd((float4*)&g_sum[cur*FCH + 8*sl],     sA);
            atomicAdd((float4*)&g_sum[cur*FCH + 8*sl + 4], sB);
            atomicAdd((float4*)&g_wx [cur*FCH + 8*sl],     wA);
            atomicAdd((float4*)&g_wx [cur*FCH + 8*sl + 4], wB);
            if (sl == 0) atomicAdd(&g_wsum[cur], aw);
        }
    }
}

// ---------------- K3: finalize + restore scratch (R13 verbatim) --------------
__global__ void k_fin(const float* __restrict__ memory, float* __restrict__ out) {
    const int c = blockIdx.x;
    const int t = threadIdx.x;
    const int cnt = g_hist[c];
    const float memv = memory[c*FCH + t];
    float res = memv;
    if (cnt > 0) {
        if (g_iszero[c] != 0.0f) {
            res = g_sum[c*FCH + t] / fmaxf((float)cnt, 1.0f);
        } else {
            const float ws = g_wsum[c];
            const float weighted = g_wx[c*FCH + t] / ((ws != 0.0f) ? ws : 1.0f);
            res = 0.9f * memv + 0.1f * weighted;
        }
    }
    out[c*FCH + t] = res;
    __syncthreads();
    if (t == 0) { g_hist[c] = 0; g_cursor[c] = 0; }
}

// ---------------- launch ----------------
extern "C" void kernel_launch(void* const* d_in, const int* in_sizes, int n_in,
                              void* d_out, int out_size) {
    const float* feats  = (const float*)d_in[0];
    const float* memory = (const float*)d_in[1];
    const int*   seg    = (const int*)  d_in[2];
    float* out = (float*)d_out;
    k_pre <<<GRID, 256>>>(feats, memory, seg);
    k_main<<<GRID, 256>>>();
    k_fin <<<NCLS, FCH>>>(memory, out);
}

// round 17
// speedup vs baseline: 1.5121x; 1.0630x over previous
#include <cuda_runtime.h>
#include <cuda_fp16.h>

#define NPIX   (480*480)
#define NCLS   124
#define FCH    64
#define IN_HW  120
#define EPS_F  1e-8f
#define GRID   444        // 148 SMs x 3 co-resident
#define NBIN   80         // bin blocks [364,444)
#define BINPX  2880       // 80*2880 = 230400
#define CH_    519        // k_main per-block range
#define PAD    32         // ints/floats per class slot = 128B (L2 sector padding)

// ---------------- device scratch (zero at first entry; restored each run) ----
__device__ __align__(16) __half g_feats_h[IN_HW*IN_HW*FCH];  // [y][x][c] fp16
__device__ __align__(16) float g_mn[NCLS*FCH];
__device__ float g_iszero[NCLS];
__device__ int   g_hist[NCLS*PAD];      // 128B-strided; reset in k_fin
__device__ int   g_cursor[NCLS*PAD];    // 128B-strided; reset in k_fin
__device__ int   g_binned[NPIX];        // pix | (cls<<18), class-contiguous
__device__ __align__(16) float g_sum[NCLS*FCH];
__device__ __align__(16) float g_wx[NCLS*FCH];
__device__ float g_wsum[NCLS*PAD];      // 128B-strided

__device__ int      g_bar_count = 0;    // bin-block barrier (reset by scanner)
__device__ unsigned g_bar_gen   = 0;    // monotonic across replays

__constant__ float c_frac[4] = {0.625f, 0.875f, 0.125f, 0.375f};

__device__ __forceinline__ __half2 u2h2(const unsigned& u) {
    return *reinterpret_cast<const __half2*>(&u);
}

// ---------------- K1: transpose | setup | bin(hist->bar(80)+scan->scatter) ---
__global__ void __launch_bounds__(256, 3)
k_pre(const float* __restrict__ feats, const float* __restrict__ memory,
      const int* __restrict__ seg) {
    __shared__ float tile[FCH*61];   // transpose buffer / bin scan scratch
    __shared__ int   h[128];
    __shared__ int      s_who;
    __shared__ unsigned s_gen;
    const int b = blockIdx.x;
    const int t = threadIdx.x;

    if (b < 240) {                   // ---- transpose half-row -> fp16, exit ----
        const int y  = b >> 1;
        const int xh = (b & 1) * 60;
        for (int i = t; i < FCH*60; i += 256) {
            int c = i / 60, x = i - c*60;
            tile[c*61 + x] = feats[c*IN_HW*IN_HW + y*IN_HW + xh + x];
        }
        __syncthreads();
        for (int i = t; i < 60*FCH; i += 256) {
            int x = i >> 6, c = i & 63;
            g_feats_h[(y*IN_HW + xh + x)*FCH + c] = __float2half(tile[c*61 + x]);
        }
        return;
    }
    if (b < 364) {                   // ---- setup class b-240, exit ----
        const int c = b - 240;
        if (t < 32) {
            float v0 = memory[c*FCH + t];
            float v1 = memory[c*FCH + t + 32];
            float s = v0*v0 + v1*v1;
            #pragma unroll
            for (int o = 16; o; o >>= 1) s += __shfl_xor_sync(0xffffffffu, s, o);
            float inv = 1.0f / fmaxf(sqrtf(s), EPS_F);
            g_mn[c*FCH + t]      = v0 * inv;
            g_mn[c*FCH + t + 32] = v1 * inv;
            if (t == 0) {
                g_iszero[c] = (s == 0.0f) ? 1.0f : 0.0f;
                g_wsum[c*PAD] = 0.0f;
            }
        } else if (t < 96) {
            g_sum[c*FCH + (t - 32)] = 0.0f;
            g_wx [c*FCH + (t - 32)] = 0.0f;
        }
        return;
    }

    // ---- bin blocks [364,444): hist -> barrier(80)+scan -> reserve -> scatter
    const int base = (b - 364) * BINPX;
    if (t < 128) h[t] = 0;
    __syncthreads();
    for (int i = t; i < BINPX; i += 256)
        atomicAdd(&h[seg[base + i]], 1);
    __syncthreads();
    if (t < NCLS && h[t]) atomicAdd(&g_hist[t*PAD], h[t]);  // RED, 128B-strided

    // barrier among the 80 bin blocks only; last arriver's block scans
    __threadfence();
    if (t == 0) {
        unsigned my = *(volatile unsigned*)&g_bar_gen;
        s_gen = my;
        int old = atomicAdd(&g_bar_count, 1);
        s_who = (old == NBIN - 1);
        if (!s_who) {
            while (*(volatile unsigned*)&g_bar_gen == my) __nanosleep(32);
        }
        __threadfence();
    }
    __syncthreads();
    if (s_who) {
        int* sc = (int*)tile;
        int hv = 0;
        if (t < 128) { hv = (t < NCLS) ? g_hist[t*PAD] : 0; sc[t] = hv; }
        __syncthreads();
        #pragma unroll
        for (int o = 1; o < 128; o <<= 1) {
            int u = (t < 128 && t >= o) ? sc[t - o] : 0;
            __syncthreads();
            if (t < 128) sc[t] += u;
            __syncthreads();
        }
        if (t < NCLS) g_cursor[t*PAD] = sc[t] - hv;         // exclusive prefix
        __threadfence();
        __syncthreads();
        if (t == 0) {
            g_bar_count = 0;
            __threadfence();
            *(volatile unsigned*)&g_bar_gen = s_gen + 1;
        }
    }
    __syncthreads();

    if (t < NCLS) {                          // depth-80, 128B-strided targets
        int cnt = h[t];
        h[t] = cnt ? atomicAdd(&g_cursor[t*PAD], cnt) : 0;
    }
    __syncthreads();
    for (int i = t; i < BINPX; i += 256) {
        int pix = base + i;
        int c = seg[pix];
        int slot = atomicAdd(&h[c], 1);                   // smem cursor
        g_binned[slot] = pix | (c << 18);
    }
}

// ---------------- K2: main (frozen body; only g_wsum index padded) -----------
__global__ void __launch_bounds__(256, 3) k_main() {
    __shared__ float tile[FCH*61];
    const int b = blockIdx.x;
    const int t = threadIdx.x;

    int* sbuf = (int*)tile;
    const int start = b * CH_;
    const int n     = min(CH_, NPIX - start);
    for (int i = t; i < n; i += 256) sbuf[i] = g_binned[start + i];
    __syncthreads();

    const int lane = t & 31;
    const int sub  = lane >> 3;
    const int sl   = lane & 7;
    const int w    = t >> 5;
    const int wch  = (n + 7) >> 3;
    const int lj0  = w * wch;
    const int ljend = min(lj0 + wch, n);

    if (lj0 < ljend) {
        const uint4* __restrict__ fth = (const uint4*)g_feats_h;
        const float4* __restrict__ mn4 = (const float4*)g_mn;

        float4 sA = {0,0,0,0}, sB = {0,0,0,0}, wA = {0,0,0,0}, wB = {0,0,0,0};
        float  aw = 0.f;
        float4 mA = {0,0,0,0}, mB = {0,0,0,0};
        int cur = -1;

        for (int lj = lj0; lj < ljend; lj += 4) {
            const int idx    = lj + sub;
            const bool valid = idx < ljend;
            const int packed = sbuf[valid ? idx : (ljend - 1)];
            const int cls = packed >> 18;
            const int pix = packed & 0x3FFFF;

            const int oy = pix / 480;
            const int ox = pix - oy*480;
            const int iy0 = (oy >> 2) + ((oy >> 1) & 1) - 1;
            const int ix0 = (ox >> 2) + ((ox >> 1) & 1) - 1;
            const float fy = c_frac[oy & 3];
            const float fx = c_frac[ox & 3];
            const int y0 = max(iy0, 0), y1 = min(iy0 + 1, IN_HW - 1);
            const int x0 = max(ix0, 0), x1 = min(ix0 + 1, IN_HW - 1);
            const float w11 = fy * fx;
            const float w10 = fy - w11;
            const float w01 = fx - w11;
            const float w00 = 1.0f - fy - fx + w11;

            const int rA = (y0*IN_HW + x0)*8, rB = (y0*IN_HW + x1)*8;
            const int rC = (y1*IN_HW + x0)*8, rD = (y1*IN_HW + x1)*8;
            const uint4 A = fth[rA + sl], B = fth[rB + sl];
            const uint4 C = fth[rC + sl], D = fth[rD + sl];

            if (__any_sync(0xffffffffu, cls != cur)) {
                if (cls != cur) {
                    if (cur >= 0) {
                        atomicAdd((float4*)&g_sum[cur*FCH + 8*sl],     sA);
                        atomicAdd((float4*)&g_sum[cur*FCH + 8*sl + 4], sB);
                        atomicAdd((float4*)&g_wx [cur*FCH + 8*sl],     wA);
                        atomicAdd((float4*)&g_wx [cur*FCH + 8*sl + 4], wB);
                        if (sl == 0) atomicAdd(&g_wsum[cur*PAD], aw);
                    }
                    sA = make_float4(0,0,0,0); sB = make_float4(0,0,0,0);
                    wA = make_float4(0,0,0,0); wB = make_float4(0,0,0,0);
                    aw = 0.f;
                    cur = cls;
                    mA = mn4[cls*16 + 2*sl];
                    mB = mn4[cls*16 + 2*sl + 1];
                }
            }

            const __half2 hw00 = __float2half2_rn(w00);
            const __half2 hw01 = __float2half2_rn(w01);
            const __half2 hw10 = __float2half2_rn(w10);
            const __half2 hw11 = __float2half2_rn(w11);

            __half2 h0 = __hmul2(hw00, u2h2(A.x));
            h0 = __hfma2(hw01, u2h2(B.x), h0);
            h0 = __hfma2(hw10, u2h2(C.x), h0);
            h0 = __hfma2(hw11, u2h2(D.x), h0);
            __half2 h1 = __hmul2(hw00, u2h2(A.y));
            h1 = __hfma2(hw01, u2h2(B.y), h1);
            h1 = __hfma2(hw10, u2h2(C.y), h1);
            h1 = __hfma2(hw11, u2h2(D.y), h1);
            __half2 h2 = __hmul2(hw00, u2h2(A.z));
            h2 = __hfma2(hw01, u2h2(B.z), h2);
            h2 = __hfma2(hw10, u2h2(C.z), h2);
            h2 = __hfma2(hw11, u2h2(D.z), h2);
            __half2 h3 = __hmul2(hw00, u2h2(A.w));
            h3 = __hfma2(hw01, u2h2(B.w), h3);
            h3 = __hfma2(hw10, u2h2(C.w), h3);
            h3 = __hfma2(hw11, u2h2(D.w), h3);

            const float2 f0 = __half22float2(h0);
            const float2 f1 = __half22float2(h1);
            const float2 f2 = __half22float2(h2);
            const float2 f3 = __half22float2(h3);

            float nsq = f0.x*f0.x + f0.y*f0.y + f1.x*f1.x + f1.y*f1.y
                      + f2.x*f2.x + f2.y*f2.y + f3.x*f3.x + f3.y*f3.y;
            float dt  = f0.x*mA.x + f0.y*mA.y + f1.x*mA.z + f1.y*mA.w
                      + f2.x*mB.x + f2.y*mB.y + f3.x*mB.z + f3.y*mB.w;
            #pragma unroll
            for (int o = 4; o; o >>= 1) {
                nsq += __shfl_xor_sync(0xffffffffu, nsq, o);
                dt  += __shfl_xor_sync(0xffffffffu, dt,  o);
            }
            const float wgt = 1.0f - dt * rsqrtf(fmaxf(nsq, 1e-16f));
            const float vv = valid ? 1.0f : 0.0f;
            const float g  = valid ? wgt : 0.0f;

            sA.x = fmaf(vv, f0.x, sA.x); sA.y = fmaf(vv, f0.y, sA.y);
            sA.z = fmaf(vv, f1.x, sA.z); sA.w = fmaf(vv, f1.y, sA.w);
            sB.x = fmaf(vv, f2.x, sB.x); sB.y = fmaf(vv, f2.y, sB.y);
            sB.z = fmaf(vv, f3.x, sB.z); sB.w = fmaf(vv, f3.y, sB.w);
            wA.x = fmaf(g, f0.x, wA.x);  wA.y = fmaf(g, f0.y, wA.y);
            wA.z = fmaf(g, f1.x, wA.z);  wA.w = fmaf(g, f1.y, wA.w);
            wB.x = fmaf(g, f2.x, wB.x);  wB.y = fmaf(g, f2.y, wB.y);
            wB.z = fmaf(g, f3.x, wB.z);  wB.w = fmaf(g, f3.y, wB.w);
            aw += g;
        }

        if (cur >= 0) {
            atomicAdd((float4*)&g_sum[cur*FCH + 8*sl],     sA);
            atomicAdd((float4*)&g_sum[cur*FCH + 8*sl + 4], sB);
            atomicAdd((float4*)&g_wx [cur*FCH + 8*sl],     wA);
            atomicAdd((float4*)&g_wx [cur*FCH + 8*sl + 4], wB);
            if (sl == 0) atomicAdd(&g_wsum[cur*PAD], aw);
        }
    }
}

// ---------------- K3: finalize + restore scratch ------------------------------
__global__ void k_fin(const float* __restrict__ memory, float* __restrict__ out) {
    const int c = blockIdx.x;
    const int t = threadIdx.x;
    const int cnt = g_hist[c*PAD];
    const float memv = memory[c*FCH + t];
    float res = memv;
    if (cnt > 0) {
        if (g_iszero[c] != 0.0f) {
            res = g_sum[c*FCH + t] / fmaxf((float)cnt, 1.0f);
        } else {
            const float ws = g_wsum[c*PAD];
            const float weighted = g_wx[c*FCH + t] / ((ws != 0.0f) ? ws : 1.0f);
            res = 0.9f * memv + 0.1f * weighted;
        }
    }
    out[c*FCH + t] = res;
    __syncthreads();
    if (t == 0) { g_hist[c*PAD] = 0; g_cursor[c*PAD] = 0; }
}

// ---------------- launch ----------------
extern "C" void kernel_launch(void* const* d_in, const int* in_sizes, int n_in,
                              void* d_out, int out_size) {
    const float* feats  = (const float*)d_in[0];
    const float* memory = (const float*)d_in[1];
    const int*   seg    = (const int*)  d_in[2];
    float* out = (float*)d_out;
    k_pre <<<GRID, 256>>>(feats, memory, seg);
    k_main<<<GRID, 256>>>();
    k_fin <<<NCLS, FCH>>>(memory, out);
}